// round 14
// baseline (speedup 1.0000x reference)
#include <cuda_runtime.h>
#include <cstdint>

#define B_SZ 64
#define T_SZ 2048
#define I_SZ 256
#define H_SZ 256
#define O_SZ 128
#define M_SZ (B_SZ * T_SZ)   // 131072 rows

// Scratch (device globals: no allocations allowed)
__device__ float g_xp1[(size_t)M_SZ * H_SZ];   // 128 MB
__device__ float g_h1 [(size_t)M_SZ * H_SZ];   // 128 MB
__device__ float g_xp2[(size_t)M_SZ * O_SZ];   //  64 MB

// ---------------------------------------------------------------------------
union f2u { float2 f; unsigned long long u; };

__device__ __forceinline__ float2 ffma2(float2 a, float2 b, float2 c) {
    f2u A, Bv, C;
    A.f = a; Bv.f = b; C.f = c;
    asm("fma.rn.f32x2 %0, %1, %2, %3;"
        : "=l"(C.u) : "l"(A.u), "l"(Bv.u), "l"(C.u));
    return C.f;
}

// Branch-free fast tanh (validated: rel_err 4.4e-7 vs 1e-3 budget)
__device__ __forceinline__ float fast_tanh(float x) {
    float ax = fabsf(x);
    float e  = __expf(-2.0f * ax);
    float t  = __fdividef(1.0f - e, 1.0f + e);
    return copysignf(t, x);
}

__device__ __forceinline__ uint32_t smem_u32(const void* p) {
    return (uint32_t)__cvta_generic_to_shared(p);
}
__device__ __forceinline__ uint32_t mapa_rank(uint32_t a, unsigned rank) {
    uint32_t r;
    asm("mapa.shared::cluster.u32 %0, %1, %2;" : "=r"(r) : "r"(a), "r"(rank));
    return r;
}
__device__ __forceinline__ void mbar_wait_acq_cluster(uint32_t mbar, uint32_t parity) {
    asm volatile(
        "{\n\t.reg .pred P;\n\t"
        "W_%=:\n\t"
        "mbarrier.try_wait.parity.acquire.cluster.shared::cta.b64 P, [%0], %1;\n\t"
        "@!P bra W_%=;\n\t}"
        :: "r"(mbar), "r"(parity) : "memory");
}

// ---------------------------------------------------------------------------
// SGEMM, double-buffered (R13, frozen)
// ---------------------------------------------------------------------------
__global__ __launch_bounds__(256, 2)
void sgemm_bias_kernel(const float* __restrict__ A,
                       const float* __restrict__ W,
                       const float* __restrict__ bias_a,
                       const float* __restrict__ bias_b,
                       float* __restrict__ C, int K, int N)
{
    constexpr int BM = 128, BN = 128, BK = 16;
    __shared__ float As[2][BK][BM];
    __shared__ float Bs[2][BK][BN];

    int tid = threadIdx.x;
    int bm = blockIdx.y * BM;
    int bn = blockIdx.x * BN;
    int tm = tid >> 4;
    int tn = tid & 15;

    int lrow0 = (tid * 2)     >> 2, lc40 = (tid * 2)     & 3;
    int lrow1 = (tid * 2 + 1) >> 2, lc41 = (tid * 2 + 1) & 3;

    float2 acc[8][4];
    #pragma unroll
    for (int i = 0; i < 8; i++)
        #pragma unroll
        for (int j = 0; j < 4; j++) acc[i][j] = make_float2(0.f, 0.f);

    const float* Ab = A + (size_t)bm * K;
    const float* Wb = W + (size_t)bn * K;

    float4 va0, va1, vb0, vb1;

    va0 = *(const float4*)(Ab + (size_t)lrow0 * K + 0 + lc40 * 4);
    va1 = *(const float4*)(Ab + (size_t)lrow1 * K + 0 + lc41 * 4);
    vb0 = *(const float4*)(Wb + (size_t)lrow0 * K + 0 + lc40 * 4);
    vb1 = *(const float4*)(Wb + (size_t)lrow1 * K + 0 + lc41 * 4);
    As[0][lc40 * 4 + 0][lrow0] = va0.x; As[0][lc40 * 4 + 1][lrow0] = va0.y;
    As[0][lc40 * 4 + 2][lrow0] = va0.z; As[0][lc40 * 4 + 3][lrow0] = va0.w;
    As[0][lc41 * 4 + 0][lrow1] = va1.x; As[0][lc41 * 4 + 1][lrow1] = va1.y;
    As[0][lc41 * 4 + 2][lrow1] = va1.z; As[0][lc41 * 4 + 3][lrow1] = va1.w;
    Bs[0][lc40 * 4 + 0][lrow0] = vb0.x; Bs[0][lc40 * 4 + 1][lrow0] = vb0.y;
    Bs[0][lc40 * 4 + 2][lrow0] = vb0.z; Bs[0][lc40 * 4 + 3][lrow0] = vb0.w;
    Bs[0][lc41 * 4 + 0][lrow1] = vb1.x; Bs[0][lc41 * 4 + 1][lrow1] = vb1.y;
    Bs[0][lc41 * 4 + 2][lrow1] = vb1.z; Bs[0][lc41 * 4 + 3][lrow1] = vb1.w;
    __syncthreads();

    int buf = 0;
    for (int kt = 0; kt < K; kt += BK) {
        int ktn = kt + BK;
        bool more = (ktn < K);
        if (more) {
            va0 = *(const float4*)(Ab + (size_t)lrow0 * K + ktn + lc40 * 4);
            va1 = *(const float4*)(Ab + (size_t)lrow1 * K + ktn + lc41 * 4);
            vb0 = *(const float4*)(Wb + (size_t)lrow0 * K + ktn + lc40 * 4);
            vb1 = *(const float4*)(Wb + (size_t)lrow1 * K + ktn + lc41 * 4);
        }

        #pragma unroll
        for (int kk = 0; kk < BK; kk++) {
            float4 a0 = *(const float4*)&As[buf][kk][tm * 8];
            float4 a1 = *(const float4*)&As[buf][kk][tm * 8 + 4];
            float4 b0 = *(const float4*)&Bs[buf][kk][tn * 8];
            float4 b1 = *(const float4*)&Bs[buf][kk][tn * 8 + 4];
            float av[8] = {a0.x, a0.y, a0.z, a0.w, a1.x, a1.y, a1.z, a1.w};
            float2 bv[4] = {make_float2(b0.x, b0.y), make_float2(b0.z, b0.w),
                            make_float2(b1.x, b1.y), make_float2(b1.z, b1.w)};
            #pragma unroll
            for (int i = 0; i < 8; i++) {
                float2 ai = make_float2(av[i], av[i]);
                #pragma unroll
                for (int j = 0; j < 4; j++)
                    acc[i][j] = ffma2(ai, bv[j], acc[i][j]);
            }
        }

        if (more) {
            int nb = buf ^ 1;
            As[nb][lc40 * 4 + 0][lrow0] = va0.x; As[nb][lc40 * 4 + 1][lrow0] = va0.y;
            As[nb][lc40 * 4 + 2][lrow0] = va0.z; As[nb][lc40 * 4 + 3][lrow0] = va0.w;
            As[nb][lc41 * 4 + 0][lrow1] = va1.x; As[nb][lc41 * 4 + 1][lrow1] = va1.y;
            As[nb][lc41 * 4 + 2][lrow1] = va1.z; As[nb][lc41 * 4 + 3][lrow1] = va1.w;
            Bs[nb][lc40 * 4 + 0][lrow0] = vb0.x; Bs[nb][lc40 * 4 + 1][lrow0] = vb0.y;
            Bs[nb][lc40 * 4 + 2][lrow0] = vb0.z; Bs[nb][lc40 * 4 + 3][lrow0] = vb0.w;
            Bs[nb][lc41 * 4 + 0][lrow1] = vb1.x; Bs[nb][lc41 * 4 + 1][lrow1] = vb1.y;
            Bs[nb][lc41 * 4 + 2][lrow1] = vb1.z; Bs[nb][lc41 * 4 + 3][lrow1] = vb1.w;
            __syncthreads();
            buf = nb;
        }
    }

    float2 bb[4];
    #pragma unroll
    for (int j = 0; j < 4; j++) {
        int n = bn + tn * 8 + j * 2;
        bb[j] = make_float2(bias_a[n] + bias_b[n], bias_a[n + 1] + bias_b[n + 1]);
    }
    #pragma unroll
    for (int i = 0; i < 8; i++) {
        int m = bm + tm * 8 + i;
        float* Crow = C + (size_t)m * N + bn + tn * 8;
        #pragma unroll
        for (int j = 0; j < 4; j++) {
            float2 v = make_float2(acc[i][j].x + bb[j].x, acc[i][j].y + bb[j].y);
            *(float2*)(Crow + j * 2) = v;
        }
    }
}

// ---------------------------------------------------------------------------
// Layer-1 scan: CLUSTER-4 per batch, psum exchange. Each CTA r holds a
// 64-input quarter of W_hh for ALL 256 outputs (thread tid == output o,
// 32 f32x2 weights) and OWNS outputs [64r, 64r+64). Per step:
//   all: s = W[:, quarter r] . h[quarter r]   (local SMEM only, ~130cyc issue)
//   non-owners (192/CTA, warp-uniform): st psum -> owner CTA pbuf[p][r][m],
//                                       arrive owner's mbar (count=192/phase)
//   owners: wait mbar, v = tanh(s + 3 peer psums + xp), write local h quarter
//   one __syncthreads. Skew <= 1 step protects double buffers (same chain
//   argument as the cluster-2 version).
// ---------------------------------------------------------------------------
__global__ void __cluster_dims__(4, 1, 1) __launch_bounds__(256, 1)
rnn_scan1_kernel(const float* __restrict__ W_hh,
                 const float* __restrict__ xp,
                 float* __restrict__ h1out)
{
    __shared__ alignas(16) float hbuf[2][64];      // local h quarter
    __shared__ alignas(16) float pbuf[2][4][64];   // [phase][sender rank][m]
    __shared__ alignas(8) unsigned long long mbar;

    int tid = threadIdx.x;          // == global output index o (0..255)
    unsigned r;
    asm("mov.u32 %0, %%cluster_ctarank;" : "=r"(r));
    int b = blockIdx.x >> 2;
    unsigned q = (unsigned)(tid >> 6);   // owner rank of this output (warp-uniform)
    int m = tid & 63;
    bool owner = (q == r);

    // Weights: W_hh[o][r*64 .. r*64+63]  (my input quarter, all outputs)
    float2 w2[32];
    {
        const float4* wp = (const float4*)(W_hh + (size_t)tid * H_SZ + (int)r * 64);
        #pragma unroll
        for (int j = 0; j < 16; j++) {
            float4 v = wp[j];
            w2[2 * j]     = make_float2(v.x, v.y);
            w2[2 * j + 1] = make_float2(v.z, v.w);
        }
    }

    if (tid < 64) hbuf[0][tid] = 0.f;            // h0 = 0 (local quarter)

    uint32_t mb = smem_u32(&mbar);
    if (tid == 0)   // 192 arrivals per phase (64 senders from each of 3 peers)
        asm volatile("mbarrier.init.shared.b64 [%0], %1;" :: "r"(mb), "r"(192) : "memory");

    // Sender targets: owner CTA q's pbuf[phase][r][m] and mbar
    uint32_t rp0 = mapa_rank(smem_u32(&pbuf[0][r][m]), q);
    uint32_t rp1 = mapa_rank(smem_u32(&pbuf[1][r][m]), q);
    uint32_t rmb = mapa_rank(mb, q);

    const float* xpb = xp + (size_t)b * T_SZ * H_SZ + tid;
    float* hob = h1out + (size_t)b * T_SZ * H_SZ + tid;

    float pf[4] = {0.f, 0.f, 0.f, 0.f};
    if (owner) {                                  // warp-uniform branch
        #pragma unroll
        for (int i = 0; i < 4; i++)
            pf[i] = __ldg(xpb + (size_t)i * H_SZ);
    }

    // mbar + h0 visible cluster-wide before any remote traffic
    asm volatile("barrier.cluster.arrive.aligned;\n\tbarrier.cluster.wait.aligned;" ::: "memory");

    int j1 = (int)((r + 1) & 3), j2 = (int)((r + 2) & 3), j3 = (int)((r + 3) & 3);

    int p = 0;
    #pragma unroll 4
    for (int t = 0; t < T_SZ; t++) {
        // psum over LOCAL h quarter (warp-broadcast float4 reads)
        const float4* hb = (const float4*)&hbuf[p][0];
        float2 a0 = make_float2(0.f, 0.f), a1 = a0, a2 = a0, a3 = a0;
        #pragma unroll
        for (int j = 0; j < 4; j++) {
            float4 h0 = hb[4 * j];
            float4 h1v = hb[4 * j + 1];
            float4 h2 = hb[4 * j + 2];
            float4 h3 = hb[4 * j + 3];
            a0 = ffma2(make_float2(h0.x,  h0.y),  w2[8 * j],     a0);
            a1 = ffma2(make_float2(h0.z,  h0.w),  w2[8 * j + 1], a1);
            a2 = ffma2(make_float2(h1v.x, h1v.y), w2[8 * j + 2], a2);
            a3 = ffma2(make_float2(h1v.z, h1v.w), w2[8 * j + 3], a3);
            a0 = ffma2(make_float2(h2.x,  h2.y),  w2[8 * j + 4], a0);
            a1 = ffma2(make_float2(h2.z,  h2.w),  w2[8 * j + 5], a1);
            a2 = ffma2(make_float2(h3.x,  h3.y),  w2[8 * j + 6], a2);
            a3 = ffma2(make_float2(h3.z,  h3.w),  w2[8 * j + 7], a3);
        }
        float s = (a0.x + a1.x) + (a2.x + a3.x) + (a0.y + a1.y) + (a2.y + a3.y);

        if (!owner) {
            // ship psum to the owner CTA; distinct addresses, parallel arrives
            uint32_t ra = p ? rp1 : rp0;
            asm volatile("st.shared::cluster.f32 [%0], %1;" :: "r"(ra), "f"(s) : "memory");
            asm volatile("mbarrier.arrive.release.cluster.shared::cluster.b64 _, [%0];"
                         :: "r"(rmb) : "memory");
        } else {
            float xv = pf[t & 3];
            int tn4 = (t + 4 < T_SZ) ? (t + 4) : (T_SZ - 1);
            pf[t & 3] = __ldg(xpb + (size_t)tn4 * H_SZ);

            mbar_wait_acq_cluster(mb, (uint32_t)p);    // 3 peers' psums landed
            float v = fast_tanh(s + pbuf[p][j1][m] + pbuf[p][j2][m]
                                  + pbuf[p][j3][m] + xv);
            hbuf[p ^ 1][m] = v;                        // local h quarter, step t+1
            hob[(size_t)t * H_SZ] = v;                 // h1 for layer-2 GEMM
        }
        __syncthreads();                               // step separator
        p ^= 1;
    }

    asm volatile("barrier.cluster.arrive.aligned;\n\tbarrier.cluster.wait.aligned;" ::: "memory");
}

// ---------------------------------------------------------------------------
// Layer-2 scan (R9 champion, verbatim): 128 threads/CTA, thread == output,
// no reduction, one STS + one STG per step.
// ---------------------------------------------------------------------------
__global__ __launch_bounds__(128, 1)
void rnn_scan2_kernel(const float* __restrict__ W_hh,
                      const float* __restrict__ xp,
                      float* __restrict__ out)
{
    __shared__ float obuf[2][O_SZ];

    int tid = threadIdx.x;      // == output index o
    int b = blockIdx.x;

    float2 w2[64];
    {
        const float4* wp = (const float4*)(W_hh + (size_t)tid * O_SZ);
        #pragma unroll
        for (int j = 0; j < 32; j++) {
            float4 v = wp[j];
            w2[2 * j]     = make_float2(v.x, v.y);
            w2[2 * j + 1] = make_float2(v.z, v.w);
        }
    }

    obuf[0][tid] = 0.f;

    const float* xpb = xp + (size_t)b * T_SZ * O_SZ + tid;
    float* ob = out + (size_t)b * T_SZ * O_SZ + tid;

    float pf[4];
    #pragma unroll
    for (int i = 0; i < 4; i++)
        pf[i] = __ldg(xpb + (size_t)i * O_SZ);

    __syncthreads();

    int p = 0;
    #pragma unroll 4
    for (int t = 0; t < T_SZ; t++) {
        float xv = pf[t & 3];
        int tn4 = (t + 4 < T_SZ) ? (t + 4) : (T_SZ - 1);
        pf[t & 3] = __ldg(xpb + (size_t)tn4 * O_SZ);

        const float4* hb = (const float4*)&obuf[p][0];     // warp-broadcast reads
        float2 a0 = make_float2(0.f, 0.f), a1 = a0, a2 = a0, a3 = a0;
        #pragma unroll
        for (int j = 0; j < 8; j++) {
            float4 h0 = hb[4 * j];
            float4 h1v = hb[4 * j + 1];
            float4 h2 = hb[4 * j + 2];
            float4 h3 = hb[4 * j + 3];
            a0 = ffma2(make_float2(h0.x,  h0.y),  w2[8 * j],     a0);
            a1 = ffma2(make_float2(h0.z,  h0.w),  w2[8 * j + 1], a1);
            a2 = ffma2(make_float2(h1v.x, h1v.y), w2[8 * j + 2], a2);
            a3 = ffma2(make_float2(h1v.z, h1v.w), w2[8 * j + 3], a3);
            a0 = ffma2(make_float2(h2.x,  h2.y),  w2[8 * j + 4], a0);
            a1 = ffma2(make_float2(h2.z,  h2.w),  w2[8 * j + 5], a1);
            a2 = ffma2(make_float2(h3.x,  h3.y),  w2[8 * j + 6], a2);
            a3 = ffma2(make_float2(h3.z,  h3.w),  w2[8 * j + 7], a3);
        }
        float s = (a0.x + a1.x) + (a2.x + a3.x) + (a0.y + a1.y) + (a2.y + a3.y);

        float v = fast_tanh(s + xv);                       // no reduction needed
        obuf[p ^ 1][tid] = v;                              // ONE STS
        ob[(size_t)t * O_SZ] = v;                          // ONE STG
        __syncthreads();
        p ^= 1;
    }
}

// ---------------------------------------------------------------------------
extern "C" void kernel_launch(void* const* d_in, const int* in_sizes, int n_in,
                              void* d_out, int out_size)
{
    const float* x     = (const float*)d_in[0];
    const float* W_ih1 = (const float*)d_in[1];
    const float* W_hh1 = (const float*)d_in[2];
    const float* b_ih1 = (const float*)d_in[3];
    const float* b_hh1 = (const float*)d_in[4];
    const float* W_ih2 = (const float*)d_in[5];
    const float* W_hh2 = (const float*)d_in[6];
    const float* b_ih2 = (const float*)d_in[7];
    const float* b_hh2 = (const float*)d_in[8];
    float* out = (float*)d_out;

    float *xp1, *h1, *xp2;
    cudaGetSymbolAddress((void**)&xp1, g_xp1);
    cudaGetSymbolAddress((void**)&h1,  g_h1);
    cudaGetSymbolAddress((void**)&xp2, g_xp2);

    // Phase 1: xp1 = x @ W_ih1^T + (b_ih1 + b_hh1)   [131072 x 256]
    dim3 g1(H_SZ / 128, M_SZ / 128);
    sgemm_bias_kernel<<<g1, 256>>>(x, W_ih1, b_ih1, b_hh1, xp1, I_SZ, H_SZ);

    // Phase 2: layer-1 recurrent scan (cluster-4 per batch, psum exchange)
    rnn_scan1_kernel<<<B_SZ * 4, 256>>>(W_hh1, xp1, h1);

    // Phase 3: xp2 = h1 @ W_ih2^T + (b_ih2 + b_hh2)  [131072 x 128]
    dim3 g2(O_SZ / 128, M_SZ / 128);
    sgemm_bias_kernel<<<g2, 256>>>(h1, W_ih2, b_ih2, b_hh2, xp2, H_SZ, O_SZ);

    // Phase 4: layer-2 recurrent scan, writes final output
    rnn_scan2_kernel<<<B_SZ, 128>>>(W_hh2, xp2, out);
}

// round 15
// speedup vs baseline: 1.5584x; 1.5584x over previous
#include <cuda_runtime.h>
#include <cstdint>

#define B_SZ 64
#define T_SZ 2048
#define I_SZ 256
#define H_SZ 256
#define O_SZ 128
#define M_SZ (B_SZ * T_SZ)   // 131072 rows

// Scratch (device globals: no allocations allowed)
__device__ float g_xp1[(size_t)M_SZ * H_SZ];   // 128 MB
__device__ float g_h1 [(size_t)M_SZ * H_SZ];   // 128 MB
__device__ float g_xp2[(size_t)M_SZ * O_SZ];   //  64 MB

// ---------------------------------------------------------------------------
union f2u { float2 f; unsigned long long u; };

__device__ __forceinline__ float2 ffma2(float2 a, float2 b, float2 c) {
    f2u A, Bv, C;
    A.f = a; Bv.f = b; C.f = c;
    asm("fma.rn.f32x2 %0, %1, %2, %3;"
        : "=l"(C.u) : "l"(A.u), "l"(Bv.u), "l"(C.u));
    return C.f;
}

// Branch-free fast tanh (validated: rel_err 4.4e-7 vs 1e-3 budget)
__device__ __forceinline__ float fast_tanh(float x) {
    float ax = fabsf(x);
    float e  = __expf(-2.0f * ax);
    float t  = __fdividef(1.0f - e, 1.0f + e);
    return copysignf(t, x);
}

__device__ __forceinline__ uint32_t smem_u32(const void* p) {
    return (uint32_t)__cvta_generic_to_shared(p);
}
__device__ __forceinline__ uint32_t mapa_peer(uint32_t a, unsigned peer) {
    uint32_t r;
    asm("mapa.shared::cluster.u32 %0, %1, %2;" : "=r"(r) : "r"(a), "r"(peer));
    return r;
}
__device__ __forceinline__ void mbar_wait_acq_cluster(uint32_t mbar, uint32_t parity) {
    asm volatile(
        "{\n\t.reg .pred P;\n\t"
        "W_%=:\n\t"
        "mbarrier.try_wait.parity.acquire.cluster.shared::cta.b64 P, [%0], %1;\n\t"
        "@!P bra W_%=;\n\t}"
        :: "r"(mbar), "r"(parity) : "memory");
}

// ---------------------------------------------------------------------------
// SGEMM, double-buffered + CONFLICT-FREE B reads: each thread owns two 4-wide
// column strips (tn*4..+3, 64+tn*4..+3) so the per-kk B loads are contiguous
// 16B chunks across tn -> all 32 bank-groups, no 4-way conflict (the R13
// layout's tn*8 stride hit bank-groups {0,8,16,24} 4x each).
// Per-column accumulation order unchanged.
// ---------------------------------------------------------------------------
__global__ __launch_bounds__(256, 2)
void sgemm_bias_kernel(const float* __restrict__ A,
                       const float* __restrict__ W,
                       const float* __restrict__ bias_a,
                       const float* __restrict__ bias_b,
                       float* __restrict__ C, int K, int N)
{
    constexpr int BM = 128, BN = 128, BK = 16;
    __shared__ float As[2][BK][BM];
    __shared__ float Bs[2][BK][BN];

    int tid = threadIdx.x;
    int bm = blockIdx.y * BM;
    int bn = blockIdx.x * BN;
    int tm = tid >> 4;
    int tn = tid & 15;

    int lrow0 = (tid * 2)     >> 2, lc40 = (tid * 2)     & 3;
    int lrow1 = (tid * 2 + 1) >> 2, lc41 = (tid * 2 + 1) & 3;

    float2 acc[8][4];
    #pragma unroll
    for (int i = 0; i < 8; i++)
        #pragma unroll
        for (int j = 0; j < 4; j++) acc[i][j] = make_float2(0.f, 0.f);

    const float* Ab = A + (size_t)bm * K;
    const float* Wb = W + (size_t)bn * K;

    float4 va0, va1, vb0, vb1;

    va0 = *(const float4*)(Ab + (size_t)lrow0 * K + 0 + lc40 * 4);
    va1 = *(const float4*)(Ab + (size_t)lrow1 * K + 0 + lc41 * 4);
    vb0 = *(const float4*)(Wb + (size_t)lrow0 * K + 0 + lc40 * 4);
    vb1 = *(const float4*)(Wb + (size_t)lrow1 * K + 0 + lc41 * 4);
    As[0][lc40 * 4 + 0][lrow0] = va0.x; As[0][lc40 * 4 + 1][lrow0] = va0.y;
    As[0][lc40 * 4 + 2][lrow0] = va0.z; As[0][lc40 * 4 + 3][lrow0] = va0.w;
    As[0][lc41 * 4 + 0][lrow1] = va1.x; As[0][lc41 * 4 + 1][lrow1] = va1.y;
    As[0][lc41 * 4 + 2][lrow1] = va1.z; As[0][lc41 * 4 + 3][lrow1] = va1.w;
    Bs[0][lc40 * 4 + 0][lrow0] = vb0.x; Bs[0][lc40 * 4 + 1][lrow0] = vb0.y;
    Bs[0][lc40 * 4 + 2][lrow0] = vb0.z; Bs[0][lc40 * 4 + 3][lrow0] = vb0.w;
    Bs[0][lc41 * 4 + 0][lrow1] = vb1.x; Bs[0][lc41 * 4 + 1][lrow1] = vb1.y;
    Bs[0][lc41 * 4 + 2][lrow1] = vb1.z; Bs[0][lc41 * 4 + 3][lrow1] = vb1.w;
    __syncthreads();

    int buf = 0;
    for (int kt = 0; kt < K; kt += BK) {
        int ktn = kt + BK;
        bool more = (ktn < K);
        if (more) {
            va0 = *(const float4*)(Ab + (size_t)lrow0 * K + ktn + lc40 * 4);
            va1 = *(const float4*)(Ab + (size_t)lrow1 * K + ktn + lc41 * 4);
            vb0 = *(const float4*)(Wb + (size_t)lrow0 * K + ktn + lc40 * 4);
            vb1 = *(const float4*)(Wb + (size_t)lrow1 * K + ktn + lc41 * 4);
        }

        #pragma unroll
        for (int kk = 0; kk < BK; kk++) {
            float4 a0 = *(const float4*)&As[buf][kk][tm * 8];
            float4 a1 = *(const float4*)&As[buf][kk][tm * 8 + 4];
            float4 b0 = *(const float4*)&Bs[buf][kk][tn * 4];        // contiguous across tn
            float4 b1 = *(const float4*)&Bs[buf][kk][64 + tn * 4];   // contiguous across tn
            float av[8] = {a0.x, a0.y, a0.z, a0.w, a1.x, a1.y, a1.z, a1.w};
            float2 bv[4] = {make_float2(b0.x, b0.y), make_float2(b0.z, b0.w),
                            make_float2(b1.x, b1.y), make_float2(b1.z, b1.w)};
            #pragma unroll
            for (int i = 0; i < 8; i++) {
                float2 ai = make_float2(av[i], av[i]);
                #pragma unroll
                for (int j = 0; j < 4; j++)
                    acc[i][j] = ffma2(ai, bv[j], acc[i][j]);
            }
        }

        if (more) {
            int nb = buf ^ 1;
            As[nb][lc40 * 4 + 0][lrow0] = va0.x; As[nb][lc40 * 4 + 1][lrow0] = va0.y;
            As[nb][lc40 * 4 + 2][lrow0] = va0.z; As[nb][lc40 * 4 + 3][lrow0] = va0.w;
            As[nb][lc41 * 4 + 0][lrow1] = va1.x; As[nb][lc41 * 4 + 1][lrow1] = va1.y;
            As[nb][lc41 * 4 + 2][lrow1] = va1.z; As[nb][lc41 * 4 + 3][lrow1] = va1.w;
            Bs[nb][lc40 * 4 + 0][lrow0] = vb0.x; Bs[nb][lc40 * 4 + 1][lrow0] = vb0.y;
            Bs[nb][lc40 * 4 + 2][lrow0] = vb0.z; Bs[nb][lc40 * 4 + 3][lrow0] = vb0.w;
            Bs[nb][lc41 * 4 + 0][lrow1] = vb1.x; Bs[nb][lc41 * 4 + 1][lrow1] = vb1.y;
            Bs[nb][lc41 * 4 + 2][lrow1] = vb1.z; Bs[nb][lc41 * 4 + 3][lrow1] = vb1.w;
            __syncthreads();
            buf = nb;
        }
    }

    // Epilogue: columns are the two remapped strips.
    float2 bb[4];
    #pragma unroll
    for (int j = 0; j < 2; j++) {
        int n = bn + tn * 4 + j * 2;
        bb[j] = make_float2(bias_a[n] + bias_b[n], bias_a[n + 1] + bias_b[n + 1]);
    }
    #pragma unroll
    for (int j = 0; j < 2; j++) {
        int n = bn + 64 + tn * 4 + j * 2;
        bb[2 + j] = make_float2(bias_a[n] + bias_b[n], bias_a[n + 1] + bias_b[n + 1]);
    }
    #pragma unroll
    for (int i = 0; i < 8; i++) {
        int m = bm + tm * 8 + i;
        float* Crow0 = C + (size_t)m * N + bn + tn * 4;
        float* Crow1 = C + (size_t)m * N + bn + 64 + tn * 4;
        #pragma unroll
        for (int j = 0; j < 2; j++) {
            float2 v = make_float2(acc[i][j].x + bb[j].x, acc[i][j].y + bb[j].y);
            *(float2*)(Crow0 + j * 2) = v;
        }
        #pragma unroll
        for (int j = 0; j < 2; j++) {
            float2 v = make_float2(acc[i][2 + j].x + bb[2 + j].x,
                                   acc[i][2 + j].y + bb[2 + j].y);
            *(float2*)(Crow1 + j * 2) = v;
        }
    }
}

// ---------------------------------------------------------------------------
// Layer-1 scan (R10/R13 CHAMPION, verbatim): cluster-2 per batch, psum
// exchange, per-lane arrives (count=128), late wait, one sync per step.
// ---------------------------------------------------------------------------
__global__ void __cluster_dims__(2, 1, 1) __launch_bounds__(256, 1)
rnn_scan1_kernel(const float* __restrict__ W_hh,
                 const float* __restrict__ xp,
                 float* __restrict__ h1out)
{
    __shared__ alignas(16) float hbuf[2][128];   // local h half, double-buffered
    __shared__ alignas(16) float pbuf[2][128];   // peer psums for my outputs
    __shared__ alignas(8) unsigned long long mbar;

    int tid = threadIdx.x;      // == global output index o (0..255)
    unsigned r;
    asm("mov.u32 %0, %%cluster_ctarank;" : "=r"(r));
    int b = blockIdx.x >> 1;
    unsigned peer = r ^ 1u;

    bool owner  = ((unsigned)(tid >> 7) == r);   // my output is in my half
    int  m      = tid & 127;                     // index within a half

    // Weights: W_hh[o][r*128 .. r*128+127]  (my input half, all outputs)
    float2 w2[64];
    {
        const float4* wp = (const float4*)(W_hh + (size_t)tid * H_SZ + (int)r * 128);
        #pragma unroll
        for (int j = 0; j < 32; j++) {
            float4 v = wp[j];
            w2[2 * j]     = make_float2(v.x, v.y);
            w2[2 * j + 1] = make_float2(v.z, v.w);
        }
    }

    if (tid < 128) hbuf[0][tid] = 0.f;           // h0 = 0 (local half)

    uint32_t mb = smem_u32(&mbar);
    if (tid == 0)   // 128 arrivals per phase (one per sending lane)
        asm volatile("mbarrier.init.shared.b64 [%0], %1;" :: "r"(mb), "r"(128) : "memory");

    uint32_t rp0 = mapa_peer(smem_u32(&pbuf[0][m]), peer);
    uint32_t rp1 = mapa_peer(smem_u32(&pbuf[1][m]), peer);
    uint32_t rmb = mapa_peer(mb, peer);

    const float* xpb = xp + (size_t)b * T_SZ * H_SZ + tid;
    float* hob = h1out + (size_t)b * T_SZ * H_SZ + tid;

    float pf[4];
    #pragma unroll
    for (int i = 0; i < 4; i++)
        pf[i] = __ldg(xpb + (size_t)i * H_SZ);

    // mbar + h0 visible cluster-wide before any remote traffic
    asm volatile("barrier.cluster.arrive.aligned;\n\tbarrier.cluster.wait.aligned;" ::: "memory");

    int p = 0;
    #pragma unroll 4
    for (int t = 0; t < T_SZ; t++) {
        float xv = pf[t & 3];
        int tn4 = (t + 4 < T_SZ) ? (t + 4) : (T_SZ - 1);
        pf[t & 3] = __ldg(xpb + (size_t)tn4 * H_SZ);

        // psum over LOCAL h half (warp-broadcast float4 reads, conflict-free)
        const float4* hb = (const float4*)&hbuf[p][0];
        float2 a0 = make_float2(0.f, 0.f), a1 = a0, a2 = a0, a3 = a0;
        #pragma unroll
        for (int j = 0; j < 8; j++) {
            float4 h0 = hb[4 * j];
            float4 h1v = hb[4 * j + 1];
            float4 h2 = hb[4 * j + 2];
            float4 h3 = hb[4 * j + 3];
            a0 = ffma2(make_float2(h0.x,  h0.y),  w2[8 * j],     a0);
            a1 = ffma2(make_float2(h0.z,  h0.w),  w2[8 * j + 1], a1);
            a2 = ffma2(make_float2(h1v.x, h1v.y), w2[8 * j + 2], a2);
            a3 = ffma2(make_float2(h1v.z, h1v.w), w2[8 * j + 3], a3);
            a0 = ffma2(make_float2(h2.x,  h2.y),  w2[8 * j + 4], a0);
            a1 = ffma2(make_float2(h2.z,  h2.w),  w2[8 * j + 5], a1);
            a2 = ffma2(make_float2(h3.x,  h3.y),  w2[8 * j + 6], a2);
            a3 = ffma2(make_float2(h3.z,  h3.w),  w2[8 * j + 7], a3);
        }
        float s = (a0.x + a1.x) + (a2.x + a3.x) + (a0.y + a1.y) + (a2.y + a3.y);

        if (!owner) {
            // ship psum to the peer (its output) + arrive; release orders store
            uint32_t ra = p ? rp1 : rp0;
            asm volatile("st.shared::cluster.f32 [%0], %1;" :: "r"(ra), "f"(s) : "memory");
            asm volatile("mbarrier.arrive.release.cluster.shared::cluster.b64 _, [%0];"
                         :: "r"(rmb) : "memory");
        }

        // late wait: peer psums for THIS step (phase p)
        mbar_wait_acq_cluster(mb, (uint32_t)p);

        if (owner) {
            float v = fast_tanh(s + pbuf[p][m] + xv);
            hbuf[p ^ 1][m] = v;                    // local h half for step t+1
            hob[(size_t)t * H_SZ] = v;             // h1 for layer-2 GEMM
        }
        __syncthreads();                           // step separator
        p ^= 1;
    }

    asm volatile("barrier.cluster.arrive.aligned;\n\tbarrier.cluster.wait.aligned;" ::: "memory");
}

// ---------------------------------------------------------------------------
// Layer-2 scan (R9 champion, verbatim): 128 threads/CTA, thread == output,
// no reduction, one STS + one STG per step.
// ---------------------------------------------------------------------------
__global__ __launch_bounds__(128, 1)
void rnn_scan2_kernel(const float* __restrict__ W_hh,
                      const float* __restrict__ xp,
                      float* __restrict__ out)
{
    __shared__ float obuf[2][O_SZ];

    int tid = threadIdx.x;      // == output index o
    int b = blockIdx.x;

    float2 w2[64];
    {
        const float4* wp = (const float4*)(W_hh + (size_t)tid * O_SZ);
        #pragma unroll
        for (int j = 0; j < 32; j++) {
            float4 v = wp[j];
            w2[2 * j]     = make_float2(v.x, v.y);
            w2[2 * j + 1] = make_float2(v.z, v.w);
        }
    }

    obuf[0][tid] = 0.f;

    const float* xpb = xp + (size_t)b * T_SZ * O_SZ + tid;
    float* ob = out + (size_t)b * T_SZ * O_SZ + tid;

    float pf[4];
    #pragma unroll
    for (int i = 0; i < 4; i++)
        pf[i] = __ldg(xpb + (size_t)i * O_SZ);

    __syncthreads();

    int p = 0;
    #pragma unroll 4
    for (int t = 0; t < T_SZ; t++) {
        float xv = pf[t & 3];
        int tn4 = (t + 4 < T_SZ) ? (t + 4) : (T_SZ - 1);
        pf[t & 3] = __ldg(xpb + (size_t)tn4 * O_SZ);

        const float4* hb = (const float4*)&obuf[p][0];     // warp-broadcast reads
        float2 a0 = make_float2(0.f, 0.f), a1 = a0, a2 = a0, a3 = a0;
        #pragma unroll
        for (int j = 0; j < 8; j++) {
            float4 h0 = hb[4 * j];
            float4 h1v = hb[4 * j + 1];
            float4 h2 = hb[4 * j + 2];
            float4 h3 = hb[4 * j + 3];
            a0 = ffma2(make_float2(h0.x,  h0.y),  w2[8 * j],     a0);
            a1 = ffma2(make_float2(h0.z,  h0.w),  w2[8 * j + 1], a1);
            a2 = ffma2(make_float2(h1v.x, h1v.y), w2[8 * j + 2], a2);
            a3 = ffma2(make_float2(h1v.z, h1v.w), w2[8 * j + 3], a3);
            a0 = ffma2(make_float2(h2.x,  h2.y),  w2[8 * j + 4], a0);
            a1 = ffma2(make_float2(h2.z,  h2.w),  w2[8 * j + 5], a1);
            a2 = ffma2(make_float2(h3.x,  h3.y),  w2[8 * j + 6], a2);
            a3 = ffma2(make_float2(h3.z,  h3.w),  w2[8 * j + 7], a3);
        }
        float s = (a0.x + a1.x) + (a2.x + a3.x) + (a0.y + a1.y) + (a2.y + a3.y);

        float v = fast_tanh(s + xv);                       // no reduction needed
        obuf[p ^ 1][tid] = v;                              // ONE STS
        ob[(size_t)t * O_SZ] = v;                          // ONE STG
        __syncthreads();
        p ^= 1;
    }
}

// ---------------------------------------------------------------------------
extern "C" void kernel_launch(void* const* d_in, const int* in_sizes, int n_in,
                              void* d_out, int out_size)
{
    const float* x     = (const float*)d_in[0];
    const float* W_ih1 = (const float*)d_in[1];
    const float* W_hh1 = (const float*)d_in[2];
    const float* b_ih1 = (const float*)d_in[3];
    const float* b_hh1 = (const float*)d_in[4];
    const float* W_ih2 = (const float*)d_in[5];
    const float* W_hh2 = (const float*)d_in[6];
    const float* b_ih2 = (const float*)d_in[7];
    const float* b_hh2 = (const float*)d_in[8];
    float* out = (float*)d_out;

    float *xp1, *h1, *xp2;
    cudaGetSymbolAddress((void**)&xp1, g_xp1);
    cudaGetSymbolAddress((void**)&h1,  g_h1);
    cudaGetSymbolAddress((void**)&xp2, g_xp2);

    // Phase 1: xp1 = x @ W_ih1^T + (b_ih1 + b_hh1)   [131072 x 256]
    dim3 g1(H_SZ / 128, M_SZ / 128);
    sgemm_bias_kernel<<<g1, 256>>>(x, W_ih1, b_ih1, b_hh1, xp1, I_SZ, H_SZ);

    // Phase 2: layer-1 recurrent scan (cluster-2 per batch, psum exchange)
    rnn_scan1_kernel<<<B_SZ * 2, 256>>>(W_hh1, xp1, h1);

    // Phase 3: xp2 = h1 @ W_ih2^T + (b_ih2 + b_hh2)  [131072 x 128]
    dim3 g2(O_SZ / 128, M_SZ / 128);
    sgemm_bias_kernel<<<g2, 256>>>(h1, W_ih2, b_ih2, b_hh2, xp2, H_SZ, O_SZ);

    // Phase 4: layer-2 recurrent scan, writes final output
    rnn_scan2_kernel<<<B_SZ, 128>>>(W_hh2, xp2, out);
}